// round 1
// baseline (speedup 1.0000x reference)
#include <cuda_runtime.h>
#include <math_constants.h>

// VQ-VAE vector quantizer forward, GB300 sm_103a.
// inputs:  d_in[0] = inputs  [64, 64, 32, 32] fp32 (NCHW)
//          d_in[1] = emb_w   [512, 64] fp32
// output:  d_out fp32, concat of (loss[1], out[64*64*32*32] NCHW, idx[65536])

#define D      64
#define K      512
#define NPIX   65536          // 64 * 32 * 32
#define BLOCK  512
#define GRID   (NPIX / BLOCK) // 128 CTAs -> single wave on 148 SMs
#define OUT_ELEMS (NPIX * D)  // 4194304
#define SMEM_BYTES ((K * D + K) * sizeof(float)) // 133120 B

__device__ float g_loss;

__global__ void vq_zero() { g_loss = 0.0f; }

__global__ __launch_bounds__(BLOCK, 1)
void vq_main(const float* __restrict__ in, const float* __restrict__ emb,
             float* __restrict__ out) {
    extern __shared__ float sm[];
    float* se = sm;          // [K][D] codebook
    float* sb = sm + K * D;  // [K]    ||e||^2
    const int tid = threadIdx.x;

    // Stage codebook in SMEM (coalesced, 64 floats/thread).
    for (int i = tid; i < K * D; i += BLOCK) se[i] = emb[i];
    __syncthreads();
    // ||e_k||^2 — tiny vs ulp(dist), any order fine; mimic rounded-square-then-add.
    for (int k = tid; k < K; k += BLOCK) {
        float s = 0.0f;
        #pragma unroll
        for (int d = 0; d < D; d++) {
            float v = se[k * D + d];
            s = __fadd_rn(s, __fmul_rn(v, v));
        }
        sb[k] = s;
    }
    __syncthreads();

    const int n  = blockIdx.x * BLOCK + tid;   // pixel id = b*1024 + h*32 + w
    const int b  = n >> 10;
    const int hw = n & 1023;
    const float* px = in + (size_t)b * (D * 1024) + hw; // inputs[b][d][hw], d-stride 1024

    float x[D];
    #pragma unroll
    for (int d = 0; d < D; d++) x[d] = px[(size_t)d << 10]; // coalesced per d across warp

    // ||x||^2: squares rounded before summation (no FMA contraction), 4 strided
    // SIMD-lane accumulators + pairwise combine (XLA-CPU/NEON-style order guess).
    float a0 = 0.f, a1 = 0.f, a2 = 0.f, a3 = 0.f;
    #pragma unroll
    for (int t = 0; t < D; t += 4) {
        a0 = __fadd_rn(a0, __fmul_rn(x[t + 0], x[t + 0]));
        a1 = __fadd_rn(a1, __fmul_rn(x[t + 1], x[t + 1]));
        a2 = __fadd_rn(a2, __fmul_rn(x[t + 2], x[t + 2]));
        a3 = __fadd_rn(a3, __fmul_rn(x[t + 3], x[t + 3]));
    }
    const float A = __fadd_rn(__fadd_rn(a0, a2), __fadd_rn(a1, a3));

    // Nearest-code search: dist_k = fl((A + B_k) - fl(2 * <x, e_k>)),
    // strict '<' keeps the lowest index on ties (matches jnp.argmin).
    float best = CUDART_INF_F;
    int bi = 0;
    for (int k = 0; k < K; k++) {
        const float4* pe = (const float4*)(se + k * D); // warp-broadcast LDS.128
        float p = 0.0f;
        #pragma unroll
        for (int t = 0; t < D / 4; t++) {
            float4 e4 = pe[t];
            p = fmaf(e4.x, x[4 * t + 0], p);
            p = fmaf(e4.y, x[4 * t + 1], p);
            p = fmaf(e4.z, x[4 * t + 2], p);
            p = fmaf(e4.w, x[4 * t + 3], p);
        }
        float dist = __fsub_rn(__fadd_rn(A, sb[k]), __fmul_rn(2.0f, p));
        if (dist < best) { best = dist; bi = k; }
    }

    // Epilogue: out = fl(x + fl(q - x)) (straight-through forward), idx, loss partial.
    float* pout = out + 1 + (size_t)b * (D * 1024) + hw;
    const float* q = se + bi * D;
    float sq = 0.0f;
    #pragma unroll
    for (int d = 0; d < D; d++) {
        float qd   = q[d];
        float diff = __fsub_rn(qd, x[d]);
        sq = fmaf(diff, diff, sq);
        pout[(size_t)d << 10] = __fadd_rn(x[d], diff);
    }
    out[1 + (size_t)OUT_ELEMS + n] = (float)bi;

    // Block reduction of squared-error partial -> single atomic per CTA.
    __syncthreads(); // everyone done reading se before we reuse sm[0..15]
    #pragma unroll
    for (int o = 16; o > 0; o >>= 1)
        sq += __shfl_down_sync(0xffffffffu, sq, o);
    if ((tid & 31) == 0) sm[tid >> 5] = sq;
    __syncthreads();
    if (tid < 16) {
        float v = sm[tid];
        #pragma unroll
        for (int o = 8; o > 0; o >>= 1)
            v += __shfl_down_sync(0xffffu, v, o);
        if (tid == 0) atomicAdd(&g_loss, v);
    }
}

__global__ void vq_final(float* __restrict__ out) {
    // mean over 2^22 elements (power of two -> exact scale), then
    // loss = q_latent + 0.25 * e_latent, both equal to the mean in forward.
    float m = g_loss * (1.0f / (float)OUT_ELEMS);
    out[0] = __fadd_rn(m, __fmul_rn(0.25f, m));
}

extern "C" void kernel_launch(void* const* d_in, const int* in_sizes, int n_in,
                              void* d_out, int out_size) {
    (void)in_sizes; (void)n_in; (void)out_size;
    cudaFuncSetAttribute(vq_main, cudaFuncAttributeMaxDynamicSharedMemorySize,
                         (int)SMEM_BYTES);
    const float* in  = (const float*)d_in[0];
    const float* emb = (const float*)d_in[1];
    float* out = (float*)d_out;

    vq_zero<<<1, 1>>>();
    vq_main<<<GRID, BLOCK, SMEM_BYTES>>>(in, emb, out);
    vq_final<<<1, 1>>>(out);
}

// round 2
// speedup vs baseline: 1.0833x; 1.0833x over previous
#include <cuda_runtime.h>
#include <math_constants.h>

// VQ-VAE vector quantizer forward, GB300 sm_103a. Round 2: packed f32x2 FMA.
// inputs:  d_in[0] = inputs  [64, 64, 32, 32] fp32 (NCHW)
//          d_in[1] = emb_w   [512, 64] fp32
// output:  d_out fp32, concat of (loss[1], out[4194304] NCHW, idx[65536])

#define D      64
#define K      512
#define NPIX   65536
#define BLOCK  512
#define GRID   (NPIX / BLOCK)   // 128 CTAs, single wave
#define OUT_ELEMS (NPIX * D)
#define SMEM_BYTES ((K * D + K) * sizeof(float)) // 133120 B

__device__ float g_part[GRID];  // per-CTA squared-error partials (no zeroing needed)

typedef unsigned long long u64;

__device__ __forceinline__ u64 ffma2(u64 a, u64 b, u64 c) {
    u64 d;
    asm("fma.rn.f32x2 %0, %1, %2, %3;" : "=l"(d) : "l"(a), "l"(b), "l"(c));
    return d;
}
__device__ __forceinline__ u64 fadd2(u64 a, u64 b) {
    u64 d;
    asm("add.rn.f32x2 %0, %1, %2;" : "=l"(d) : "l"(a), "l"(b));
    return d;
}
__device__ __forceinline__ u64 pack2(float lo, float hi) {
    u64 d;
    asm("mov.b64 %0, {%1, %2};" : "=l"(d) : "f"(lo), "f"(hi));
    return d;
}
__device__ __forceinline__ void unpack2(u64 v, float& lo, float& hi) {
    asm("mov.b64 {%0, %1}, %2;" : "=f"(lo), "=f"(hi) : "l"(v));
}

__global__ __launch_bounds__(BLOCK, 1)
void vq_main(const float* __restrict__ in, const float* __restrict__ emb,
             float* __restrict__ out) {
    extern __shared__ float sm[];
    float* se = sm;          // [K][D] codebook
    float* sb = sm + K * D;  // [K]    ||e||^2
    const int tid = threadIdx.x;

    for (int i = tid; i < K * D; i += BLOCK) se[i] = emb[i];
    __syncthreads();
    for (int k = tid; k < K; k += BLOCK) {
        float s = 0.0f;
        #pragma unroll
        for (int d = 0; d < D; d++) {
            float v = se[k * D + d];
            s = __fadd_rn(s, __fmul_rn(v, v));
        }
        sb[k] = s;
    }
    __syncthreads();

    const int n  = blockIdx.x * BLOCK + tid;
    const int b  = n >> 10;
    const int hw = n & 1023;
    const float* px = in + (size_t)b * (D * 1024) + hw;

    // Load x (coalesced across warp per d), compute A with the Round-1 order
    // (rounded squares, 4 strided lanes, pairwise combine), pack into f32x2.
    u64 x2[D / 2];
    float a0 = 0.f, a1 = 0.f, a2 = 0.f, a3 = 0.f;
    #pragma unroll
    for (int t = 0; t < D; t += 4) {
        float v0 = px[(size_t)(t + 0) << 10];
        float v1 = px[(size_t)(t + 1) << 10];
        float v2 = px[(size_t)(t + 2) << 10];
        float v3 = px[(size_t)(t + 3) << 10];
        a0 = __fadd_rn(a0, __fmul_rn(v0, v0));
        a1 = __fadd_rn(a1, __fmul_rn(v1, v1));
        a2 = __fadd_rn(a2, __fmul_rn(v2, v2));
        a3 = __fadd_rn(a3, __fmul_rn(v3, v3));
        x2[t / 2]     = pack2(v0, v1);
        x2[t / 2 + 1] = pack2(v2, v3);
    }
    const float A = __fadd_rn(__fadd_rn(a0, a2), __fadd_rn(a1, a3));

    // Nearest-code search. dist_k = fl((A + B_k) - fl(2 * p_k)); p_k's rounding
    // order is non-binding (proven R1: 0 flips vs XLA's GEMM order).
    float best = CUDART_INF_F;
    int bi = 0;
    for (int k = 0; k < K; k++) {
        const ulonglong2* pe = (const ulonglong2*)(se + k * D); // LDS.128 broadcast
        u64 acc0 = 0ull, acc1 = 0ull; // packed {+0,+0}
        #pragma unroll
        for (int t = 0; t < 8; t++) {
            ulonglong2 ea = pe[2 * t];
            ulonglong2 eb = pe[2 * t + 1];
            acc0 = ffma2(ea.x, x2[4 * t + 0], acc0);
            acc1 = ffma2(ea.y, x2[4 * t + 1], acc1);
            acc0 = ffma2(eb.x, x2[4 * t + 2], acc0);
            acc1 = ffma2(eb.y, x2[4 * t + 3], acc1);
        }
        float lo, hi;
        unpack2(fadd2(acc0, acc1), lo, hi);
        float p = __fadd_rn(lo, hi);
        float dist = __fsub_rn(__fadd_rn(A, sb[k]), __fmul_rn(2.0f, p));
        if (dist < best) { best = dist; bi = k; } // strict '<': lowest index on ties
    }

    // Epilogue: out = fl(x + fl(q - x)), idx, per-thread squared error.
    float* pout = out + 1 + (size_t)b * (D * 1024) + hw;
    const float* q = se + bi * D;
    float sq = 0.0f;
    #pragma unroll
    for (int t = 0; t < D / 2; t++) {
        float xl, xh;
        unpack2(x2[t], xl, xh);
        float ql = q[2 * t], qh = q[2 * t + 1];
        float dl = __fsub_rn(ql, xl), dh = __fsub_rn(qh, xh);
        sq = fmaf(dl, dl, sq);
        sq = fmaf(dh, dh, sq);
        pout[(size_t)(2 * t)     << 10] = __fadd_rn(xl, dl);
        pout[(size_t)(2 * t + 1) << 10] = __fadd_rn(xh, dh);
    }
    out[1 + (size_t)OUT_ELEMS + n] = (float)bi;

    // Block reduction -> one deterministic per-CTA partial (no atomics, no zeroing).
    __syncthreads(); // done reading se; reuse sm[0..15]
    #pragma unroll
    for (int o = 16; o > 0; o >>= 1)
        sq += __shfl_down_sync(0xffffffffu, sq, o);
    if ((tid & 31) == 0) sm[tid >> 5] = sq;
    __syncthreads();
    if (tid < 16) {
        float v = sm[tid];
        #pragma unroll
        for (int o = 8; o > 0; o >>= 1)
            v += __shfl_down_sync(0xffffu, v, o);
        if (tid == 0) g_part[blockIdx.x] = v;
    }
}

__global__ void vq_final(float* __restrict__ out) {
    float s = 0.0f;
    #pragma unroll
    for (int i = 0; i < GRID; i++) s += g_part[i];
    float m = s * (1.0f / (float)OUT_ELEMS);
    out[0] = __fadd_rn(m, __fmul_rn(0.25f, m));
}

extern "C" void kernel_launch(void* const* d_in, const int* in_sizes, int n_in,
                              void* d_out, int out_size) {
    (void)in_sizes; (void)n_in; (void)out_size;
    cudaFuncSetAttribute(vq_main, cudaFuncAttributeMaxDynamicSharedMemorySize,
                         (int)SMEM_BYTES);
    const float* in  = (const float*)d_in[0];
    const float* emb = (const float*)d_in[1];
    float* out = (float*)d_out;

    vq_main<<<GRID, BLOCK, SMEM_BYTES>>>(in, emb, out);
    vq_final<<<1, 1>>>(out);
}